// round 16
// baseline (speedup 1.0000x reference)
#include <cuda_runtime.h>
#include <cstdint>
#include <math.h>

#define B_    64
#define N_    4096
#define D_    128
#define E_    512
#define S_    16                // contiguous 256-slot segments per batch
#define SEG   (N_/S_)           // 256
#define TS    32                // slots per bulk tile (16KB)
#define GRID2 (B_*S_)           // 1024

typedef unsigned long long u64;

// ---- packed f32x2 helpers (sm_103a FFMA2 pipe) ----
__device__ __forceinline__ u64 f2mul(u64 a, u64 b) {
    u64 r; asm("mul.rn.f32x2 %0, %1, %2;" : "=l"(r) : "l"(a), "l"(b)); return r;
}
__device__ __forceinline__ u64 f2fma(u64 a, u64 b, u64 c) {
    u64 r; asm("fma.rn.f32x2 %0, %1, %2, %3;" : "=l"(r) : "l"(a), "l"(b), "l"(c)); return r;
}
__device__ __forceinline__ float f2hadd(u64 v) {
    float lo, hi; asm("mov.b64 {%0,%1}, %2;" : "=f"(lo), "=f"(hi) : "l"(v));
    return lo + hi;
}
__device__ __forceinline__ u64 f2pack(float x) {
    u64 r; asm("mov.b64 %0, {%1,%1};" : "=l"(r) : "f"(x)); return r;
}
__device__ __forceinline__ unsigned smem_u32(const void* p) {
    unsigned r;
    asm("{ .reg .u64 t; cvta.to.shared.u64 t, %1; cvt.u32.u64 %0, t; }"
        : "=r"(r) : "l"(p));
    return r;
}

#define MBAR_INIT(a, c) \
    asm volatile("mbarrier.init.shared.b64 [%0], %1;" :: "r"(a), "r"(c) : "memory")
#define MBAR_EXPECT(a, bytes) \
    asm volatile("mbarrier.arrive.expect_tx.shared.b64 _, [%0], %1;" \
                 :: "r"(a), "r"(bytes) : "memory")
#define MBAR_ARRIVE(a) \
    asm volatile("mbarrier.arrive.shared.b64 _, [%0];" :: "r"(a) : "memory")
#define MBAR_WAIT(a, par) do {                                              \
    unsigned _done;                                                         \
    asm volatile("{\n\t.reg .pred p;\n\t"                                   \
        "mbarrier.try_wait.parity.acquire.cta.shared::cta.b64 p, [%1], %2;\n\t" \
        "selp.b32 %0, 1, 0, p;\n\t}"                                        \
        : "=r"(_done) : "r"(a), "r"(par) : "memory");                       \
    while (!_done) {                                                        \
        asm volatile("{\n\t.reg .pred p;\n\t"                               \
            "mbarrier.try_wait.parity.acquire.cta.shared::cta.b64 p, [%1], %2, 0x989680;\n\t" \
            "selp.b32 %0, 1, 0, p;\n\t}"                                    \
            : "=r"(_done) : "r"(a), "r"(par) : "memory");                   \
    }                                                                       \
} while (0)
#define BULK_LD(dst, src, sz, mbar) \
    asm volatile("cp.async.bulk.shared::cta.global.mbarrier::complete_tx::bytes " \
                 "[%0], [%1], %2, [%3];" \
                 :: "r"(dst), "l"(src), "r"(sz), "r"(mbar) : "memory")

// ---- device scratch (no allocations; 16B-aligned for vector access) ----
// Replay-safe: g_fin is a cumulative monotonic counter (mod-GRID2 test);
// data arrays are rewritten with identical values each replay before reads.
__device__ __align__(16) float g_q  [B_*D_];
__device__ __align__(16) float g_qa [B_*D_];
__device__ __align__(16) float g_pacc[B_*S_*D_];
__device__ float g_ps [B_*S_];
__device__ int   g_fin;

// ============================================================
// Kernel 1: proj_q = vecQ @ Wq^T + bq ; qa = q * Wa. (R15-proven)
// ============================================================
__global__ void __launch_bounds__(256)
proj_kernel(const float* __restrict__ vq,
            const float* __restrict__ Wq,
            const float* __restrict__ bq,
            const float* __restrict__ Wa)
{
    const int warp = threadIdx.x >> 5;
    const int lane = threadIdx.x & 31;
    const int wg   = blockIdx.x * 8 + warp;    // 0..2047
    const int b    = wg >> 5;
    const int d0   = (wg & 31) * 4;

    const float4* v4 = (const float4*)(vq + (size_t)b * E_);
    float4 v[4];
    #pragma unroll
    for (int j = 0; j < 4; j++) v[j] = v4[j*32 + lane];

    float a[4];
    #pragma unroll
    for (int t = 0; t < 4; t++) {
        const float4* w4 = (const float4*)(Wq + (size_t)(d0 + t) * E_);
        float acc = 0.f;
        #pragma unroll
        for (int j = 0; j < 4; j++) {
            float4 y = w4[j*32 + lane];
            acc += v[j].x*y.x + v[j].y*y.y + v[j].z*y.z + v[j].w*y.w;
        }
        a[t] = acc;
    }
    #pragma unroll
    for (int t = 0; t < 4; t++) {
        #pragma unroll
        for (int off = 16; off > 0; off >>= 1)
            a[t] += __shfl_xor_sync(0xffffffffu, a[t], off);
    }
    if (lane < 4) {
        const int d = d0 + lane;
        float qv = a[lane] + bq[d];
        g_q [b*D_ + d] = qv;
        g_qa[b*D_ + d] = qv * Wa[d];
    }
}

// ============================================================
// Kernel 2: att pass, cp.async.bulk 16KB-tile pipeline (2-deep ring),
// contiguous 256-slot segments, warp-per-4-slots consumption with
// packed-f32x2 math, fused ticket combine.
// ============================================================
__global__ void __launch_bounds__(256)
att_kernel(const float* __restrict__ kb,
           const int*   __restrict__ ion,
           const float* __restrict__ Wa,
           const float* __restrict__ ba_p,
           float*       __restrict__ out)
{
    const int tid   = threadIdx.x;
    const int warp  = tid >> 5, lane = tid & 31;
    const int bs    = blockIdx.x;
    const int b     = bs >> 4;          // / S_
    const int split = bs & (S_ - 1);

    __shared__ __align__(128) float4 sbuf[2][TS*32];   // 32KB tile ring
    __shared__ __align__(8)  u64 mb_full[2], mb_empty[2];
    __shared__ __align__(16) float sacc[8][132];
    __shared__ float ssum[8];
    __shared__ int   scnt;
    __shared__ float sM, sba;
    __shared__ int   sticket;

    // ---- per-block meta ----
    if (warp == 0) {
        // int64 vs int32 decode: values in [0,4096); if int64 (LE) every odd
        // 32-bit word of the first 64 is 0. Detection reads stay in first
        // 256B; word 2*b (<=508B) read only when layout is int64 (512B alloc).
        bool oz   = (ion[2*lane + 1] == 0);
        bool is64 = __all_sync(0xffffffffu, oz);
        if (lane == 0) scnt = is64 ? ion[2*b] : ion[b];
    } else if (warp == 1) {
        // M = max(ba + ||Wa||, 0) >= every logit (Cauchy-Schwarz)
        float t = 0.f;
        #pragma unroll
        for (int i = 0; i < 4; i++) { float wv = Wa[i*32 + lane]; t += wv*wv; }
        #pragma unroll
        for (int off = 16; off > 0; off >>= 1)
            t += __shfl_xor_sync(0xffffffffu, t, off);
        if (lane == 0) { float ba = *ba_p; sba = ba; sM = fmaxf(ba + sqrtf(t), 0.f); }
    }
    const unsigned fullA  = smem_u32(&mb_full[0]);
    const unsigned emptyA = smem_u32(&mb_empty[0]);
    if (tid == 0) {
        MBAR_INIT(fullA,      1u);  MBAR_INIT(fullA + 8,  1u);
        MBAR_INIT(emptyA,     8u);  MBAR_INIT(emptyA + 8, 8u);
    }
    __syncthreads();                 // publish meta + barrier init

    const int   cnt     = scnt;
    const int   limit   = (cnt == 0) ? N_ : cnt;
    const bool  uniform = (cnt == 0);
    const float M  = sM;
    const float ba = sba;

    const int s0 = split * SEG;
    const int n1 = min(s0 + SEG, limit);

    float s = 0.f;
    u64 accx = 0ull, accy = 0ull;

    if (s0 < n1) {
        const int T = (n1 - s0 + TS - 1) / TS;
        const float* kbB = kb + (size_t)b * N_ * D_;
        const unsigned buf0 = smem_u32(&sbuf[0][0]);

        // prologue: issue tiles 0 and 1
        if (tid == 0) {
            #pragma unroll
            for (int t = 0; t < 2; t++) {
                if (t < T) {
                    const int st = s0 + TS * t;
                    const unsigned bytes = (unsigned)(min(TS, n1 - st)) * 512u;
                    MBAR_EXPECT(fullA + 8u*t, bytes);
                    BULK_LD(buf0 + 16384u*t, kbB + (size_t)st * D_, bytes,
                            fullA + 8u*t);
                }
            }
        }

        // q,qa: lane's 4 floats (dims 4*lane..+3) as packed f32x2
        const ulonglong2 q2  = ((const ulonglong2*)(g_q  + b*D_))[lane];
        const ulonglong2 qa2 = ((const ulonglong2*)(g_qa + b*D_))[lane];

        for (int t = 0; t < T; t++) {
            const unsigned bsel = (unsigned)(t & 1);
            const unsigned par  = (unsigned)((t >> 1) & 1);
            MBAR_WAIT(fullA + 8u*bsel, par);

            const int st   = s0 + TS * t;
            const int rows = min(TS, n1 - st);
            const ulonglong2* buf = (const ulonglong2*)&sbuf[bsel][0];

            #pragma unroll
            for (int i = 0; i < 4; i++) {
                const int row = warp * 4 + i;           // uniform per warp
                if (row < rows) {
                    ulonglong2 k2 = buf[row*32 + lane];
                    u64 ipx  = f2mul(k2.x, q2.x);
                    u64 ipy  = f2mul(k2.y, q2.y);
                    u64 nrm2 = f2fma(ipy, ipy, f2mul(ipx, ipx));
                    nrm2     = f2fma(ipx, ipx, f2mul(ipy, ipy)); // keep simple
                    // recompute cleanly (compiler CSEs):
                    nrm2 = f2fma(ipx, ipx, (u64)0ull);
                    nrm2 = f2fma(ipy, ipy, nrm2);
                    u64 dot2 = f2fma(k2.x, qa2.x, (u64)0ull);
                    dot2     = f2fma(k2.y, qa2.y, dot2);
                    float dot = f2hadd(dot2);
                    float nrm = f2hadd(nrm2);
                    #pragma unroll
                    for (int off = 16; off > 0; off >>= 1) {
                        dot += __shfl_xor_sync(0xffffffffu, dot, off);
                        nrm += __shfl_xor_sync(0xffffffffu, nrm, off);
                    }
                    float L = uniform ? 0.f
                                      : (dot * rsqrtf(fmaxf(nrm, 1e-24f)) + ba);
                    float w = __expf(L - M);           // L <= M: no overflow
                    s += w;
                    u64 ww = f2pack(w);
                    accx = f2fma(k2.x, ww, accx);
                    accy = f2fma(k2.y, ww, accy);
                }
            }
            __syncwarp();
            if (lane == 0) MBAR_ARRIVE(emptyA + 8u*bsel);

            if (tid == 0 && t + 2 < T) {
                MBAR_WAIT(emptyA + 8u*bsel, par);      // all 8 warps done
                const int st2 = s0 + TS * (t + 2);
                const unsigned bytes = (unsigned)(min(TS, n1 - st2)) * 512u;
                MBAR_EXPECT(fullA + 8u*bsel, bytes);
                BULK_LD(buf0 + 16384u*bsel, kbB + (size_t)st2 * D_, bytes,
                        fullA + 8u*bsel);
            }
        }
    }

    // ---- reduce 8 warps; every block writes its partial (zeros if empty) ----
    *(ulonglong2*)&sacc[warp][lane*4] = make_ulonglong2(accx, accy);
    if (lane == 0) ssum[warp] = s;
    __syncthreads();

    if (tid < D_) {
        float a = 0.f;
        #pragma unroll
        for (int j = 0; j < 8; j++) a += sacc[j][tid];
        g_pacc[bs*D_ + tid] = a;
    } else if (tid == D_) {
        float t2 = 0.f;
        #pragma unroll
        for (int j = 0; j < 8; j++) t2 += ssum[j];
        g_ps[bs] = t2;
    }

    // ---- ticket; last 64 ticket-takers combine one batch each ----
    __threadfence();
    __syncthreads();
    if (tid == 0) sticket = atomicAdd(&g_fin, 1);     // cumulative
    __syncthreads();
    const int pos   = sticket % GRID2;
    const int tbase = sticket - pos;
    if (pos >= GRID2 - B_) {
        const int cb = pos - (GRID2 - B_);            // batch to combine
        if (tid == 0) {
            while (*((volatile int*)&g_fin) < tbase + GRID2) __nanosleep(64);
        }
        __syncthreads();
        __threadfence();
        if (tid < D_) {
            float ss = 0.f, av = 0.f;
            #pragma unroll
            for (int i = 0; i < S_; i++) {
                ss += __ldcg(&g_ps[cb*S_ + i]);
                av += __ldcg(&g_pacc[(cb*S_ + i)*D_ + tid]);
            }
            out[cb*D_ + tid] = av / ss;               // ss > 0 (limit >= 1)
        }
    }
}

extern "C" void kernel_launch(void* const* d_in, const int* in_sizes, int n_in,
                              void* d_out, int out_size)
{
    const float* kb  = (const float*)d_in[0];
    const float* vq  = (const float*)d_in[1];
    const int*   ion = (const int*)  d_in[2];   // int32 or int64, auto-detected
    const float* Wq  = (const float*)d_in[3];
    const float* bq  = (const float*)d_in[4];
    const float* Wa  = (const float*)d_in[5];
    const float* ba  = (const float*)d_in[6];
    float* out = (float*)d_out;

    proj_kernel<<<256,   256>>>(vq, Wq, bq, Wa);
    att_kernel <<<GRID2, 256>>>(kb, ion, Wa, ba, out);
}

// round 17
// speedup vs baseline: 1.3122x; 1.3122x over previous
#include <cuda_runtime.h>
#include <cstdint>
#include <math.h>

#define B_    64
#define N_    4096
#define D_    128
#define E_    512
#define S_    16                // N-splits per batch -> att grid 1024
#define GPB   16                // 16-lane groups per att block
#define TSTREAMS (S_*GPB)       // 256 interleaved slot streams per batch
#define GRID2 (B_*S_)           // 1024

typedef unsigned long long u64;

// ---- packed f32x2 helpers (sm_103a FFMA2 pipe) ----
__device__ __forceinline__ u64 f2mul(u64 a, u64 b) {
    u64 r; asm("mul.rn.f32x2 %0, %1, %2;" : "=l"(r) : "l"(a), "l"(b)); return r;
}
__device__ __forceinline__ u64 f2fma(u64 a, u64 b, u64 c) {
    u64 r; asm("fma.rn.f32x2 %0, %1, %2, %3;" : "=l"(r) : "l"(a), "l"(b), "l"(c)); return r;
}
__device__ __forceinline__ float f2hadd(u64 v) {
    float lo, hi; asm("mov.b64 {%0,%1}, %2;" : "=f"(lo), "=f"(hi) : "l"(v));
    return lo + hi;
}
__device__ __forceinline__ u64 f2pack(float x) {
    u64 r; asm("mov.b64 %0, {%1,%1};" : "=l"(r) : "f"(x)); return r;
}

// ---- device scratch (no allocations; 16B-aligned for vector access) ----
// Replay-safe: g_fin is a cumulative monotonic counter (mod-GRID2 test);
// data arrays are rewritten with identical values each replay before reads.
__device__ __align__(16) float g_q  [B_*D_];
__device__ __align__(16) float g_qa [B_*D_];
__device__ __align__(16) float g_pacc[B_*S_*D_];
__device__ float g_ps [B_*S_];
__device__ int   g_fin;

// ============================================================
// Kernel 1: proj_q = vecQ @ Wq^T + bq ; qa = q * Wa. (R15-proven)
// ============================================================
__global__ void __launch_bounds__(256)
proj_kernel(const float* __restrict__ vq,
            const float* __restrict__ Wq,
            const float* __restrict__ bq,
            const float* __restrict__ Wa)
{
    const int warp = threadIdx.x >> 5;
    const int lane = threadIdx.x & 31;
    const int wg   = blockIdx.x * 8 + warp;    // 0..2047
    const int b    = wg >> 5;
    const int d0   = (wg & 31) * 4;

    const float4* v4 = (const float4*)(vq + (size_t)b * E_);
    float4 v[4];
    #pragma unroll
    for (int j = 0; j < 4; j++) v[j] = v4[j*32 + lane];

    float a[4];
    #pragma unroll
    for (int t = 0; t < 4; t++) {
        const float4* w4 = (const float4*)(Wq + (size_t)(d0 + t) * E_);
        float acc = 0.f;
        #pragma unroll
        for (int j = 0; j < 4; j++) {
            float4 y = w4[j*32 + lane];
            acc += v[j].x*y.x + v[j].y*y.y + v[j].z*y.z + v[j].w*y.w;
        }
        a[t] = acc;
    }
    #pragma unroll
    for (int t = 0; t < 4; t++) {
        #pragma unroll
        for (int off = 16; off > 0; off >>= 1)
            a[t] += __shfl_xor_sync(0xffffffffu, a[t], off);
    }
    if (lane < 4) {
        const int d = d0 + lane;
        float qv = a[lane] + bq[d];
        g_q [b*D_ + d] = qv;
        g_qa[b*D_ + d] = qv * Wa[d];
    }
}

// ============================================================
// Kernel 2: att pass, 16-lane groups (low regs -> 4 CTAs/SM),
// packed-f32x2 math, __ldcg loads, 2-slot batching, fixed-reference
// weights w = exp(L - M); fused ticket combine.
// ============================================================
__global__ void __launch_bounds__(256, 4)
att_kernel(const float* __restrict__ kb,
           const int*   __restrict__ ion,
           const float* __restrict__ Wa,
           const float* __restrict__ ba_p,
           float*       __restrict__ out)
{
    const int tid   = threadIdx.x;
    const int warp  = tid >> 5, lane = tid & 31;
    const int bs    = blockIdx.x;
    const int b     = bs >> 4;          // / S_
    const int split = bs & (S_ - 1);
    const int g     = lane >> 4, sub = lane & 15;
    const int gid   = warp * 2 + g;     // 0..15

    __shared__ int   scnt;
    __shared__ float sM, sba;
    __shared__ __align__(16) float sacc[GPB][132];
    __shared__ float ssum[GPB];
    __shared__ int   sticket;

    // ---- per-block meta ----
    if (warp == 0) {
        // int64 vs int32 decode: values in [0,4096); if int64 (LE) every odd
        // 32-bit word of the first 64 is 0. Detection reads stay in first
        // 256B; word 2*b (<=508B) read only when layout is int64 (512B alloc).
        bool oz   = (ion[2*lane + 1] == 0);
        bool is64 = __all_sync(0xffffffffu, oz);
        if (lane == 0) scnt = is64 ? ion[2*b] : ion[b];
    } else if (warp == 1) {
        // M = max(ba + ||Wa||, 0) >= every logit (Cauchy-Schwarz)
        float t = 0.f;
        #pragma unroll
        for (int i = 0; i < 4; i++) { float wv = Wa[i*32 + lane]; t += wv*wv; }
        #pragma unroll
        for (int off = 16; off > 0; off >>= 1)
            t += __shfl_xor_sync(0xffffffffu, t, off);
        if (lane == 0) { float ba = *ba_p; sba = ba; sM = fmaxf(ba + sqrtf(t), 0.f); }
    }
    __syncthreads();

    const int   cnt     = scnt;
    const int   limit   = (cnt == 0) ? N_ : cnt;
    const bool  uniform = (cnt == 0);
    const float M  = sM;
    const float ba = sba;

    // q,qa: this lane's 8 floats (ulonglong2 rows sub and sub+16)
    ulonglong2 q2[2], qa2[2];
    #pragma unroll
    for (int i = 0; i < 2; i++) {
        q2[i]  = ((const ulonglong2*)(g_q  + b*D_))[i*16 + sub];
        qa2[i] = ((const ulonglong2*)(g_qa + b*D_))[i*16 + sub];
    }

    const ulonglong2* kb2 = (const ulonglong2*)(kb + (size_t)b * N_ * D_);

    float s = 0.f;
    ulonglong2 acc2[2];
    #pragma unroll
    for (int i = 0; i < 2; i++) { acc2[i].x = 0ull; acc2[i].y = 0ull; }

    // two slots per group per iteration; out-of-range slots clamp to
    // limit-1 and are annihilated by w=0 (clamped values stay finite).
    for (int n0 = split*GPB + gid; __any_sync(0xffffffffu, n0 < limit);
         n0 += 2*TSTREAMS) {
        const int  n1 = n0 + TSTREAMS;
        const bool v0 = n0 < limit;
        const bool v1 = n1 < limit;
        const int  m0 = min(n0, limit - 1);
        const int  m1 = min(n1, limit - 1);

        ulonglong2 k0[2], k1[2];
        #pragma unroll
        for (int i = 0; i < 2; i++)
            k0[i] = __ldcg(&kb2[(size_t)m0*32 + i*16 + sub]);
        #pragma unroll
        for (int i = 0; i < 2; i++)
            k1[i] = __ldcg(&kb2[(size_t)m1*32 + i*16 + sub]);

        #pragma unroll
        for (int t = 0; t < 2; t++) {
            ulonglong2* k = t ? k1 : k0;
            const bool v = t ? v1 : v0;
            u64 dot2 = 0ull, nrm2 = 0ull;
            #pragma unroll
            for (int i = 0; i < 2; i++) {
                u64 ipx = f2mul(k[i].x, q2[i].x);
                u64 ipy = f2mul(k[i].y, q2[i].y);
                nrm2 = f2fma(ipx, ipx, nrm2);
                nrm2 = f2fma(ipy, ipy, nrm2);
                dot2 = f2fma(k[i].x, qa2[i].x, dot2);
                dot2 = f2fma(k[i].y, qa2[i].y, dot2);
            }
            float dot = f2hadd(dot2);
            float nrm = f2hadd(nrm2);
            #pragma unroll
            for (int off = 8; off > 0; off >>= 1) {   // 16-lane reduce
                dot += __shfl_xor_sync(0xffffffffu, dot, off);
                nrm += __shfl_xor_sync(0xffffffffu, nrm, off);
            }
            float L = uniform ? 0.f : (dot * rsqrtf(fmaxf(nrm, 1e-24f)) + ba);
            float w = v ? __expf(L - M) : 0.f;    // L <= M: never overflows
            s += w;
            u64 ww = f2pack(w);
            #pragma unroll
            for (int i = 0; i < 2; i++) {
                acc2[i].x = f2fma(k[i].x, ww, acc2[i].x);
                acc2[i].y = f2fma(k[i].y, ww, acc2[i].y);
            }
        }
    }

    // merge 16 groups of this CTA (132-stride: aligned, conflict-free)
    #pragma unroll
    for (int i = 0; i < 2; i++)
        *(ulonglong2*)&sacc[gid][(i*16 + sub)*4] = acc2[i];
    if (sub == 0) ssum[gid] = s;
    __syncthreads();

    if (tid < D_) {
        float a = 0.f;
        #pragma unroll
        for (int j = 0; j < GPB; j++) a += sacc[j][tid];
        g_pacc[bs*D_ + tid] = a;
    } else if (tid == D_) {
        float t = 0.f;
        #pragma unroll
        for (int j = 0; j < GPB; j++) t += ssum[j];
        g_ps[bs] = t;
    }

    // ---- ticket; last 64 ticket-takers combine one batch each ----
    __threadfence();
    __syncthreads();
    if (tid == 0) sticket = atomicAdd(&g_fin, 1);     // cumulative
    __syncthreads();
    const int pos   = sticket % GRID2;
    const int tbase = sticket - pos;
    if (pos >= GRID2 - B_) {
        const int cb = pos - (GRID2 - B_);            // batch to combine
        if (tid == 0) {                               // wait for all blocks
            while (*((volatile int*)&g_fin) < tbase + GRID2) __nanosleep(64);
        }
        __syncthreads();
        __threadfence();
        if (tid < D_) {
            float ss = 0.f, av = 0.f;
            #pragma unroll
            for (int i = 0; i < S_; i++) {
                ss += __ldcg(&g_ps[cb*S_ + i]);
                av += __ldcg(&g_pacc[(cb*S_ + i)*D_ + tid]);
            }
            out[cb*D_ + tid] = av / ss;               // ss > 0 (limit >= 1)
        }
    }
}

extern "C" void kernel_launch(void* const* d_in, const int* in_sizes, int n_in,
                              void* d_out, int out_size)
{
    const float* kb  = (const float*)d_in[0];
    const float* vq  = (const float*)d_in[1];
    const int*   ion = (const int*)  d_in[2];   // int32 or int64, auto-detected
    const float* Wq  = (const float*)d_in[3];
    const float* bq  = (const float*)d_in[4];
    const float* Wa  = (const float*)d_in[5];
    const float* ba  = (const float*)d_in[6];
    float* out = (float*)d_out;

    proj_kernel<<<256,   256>>>(vq, Wq, bq, Wa);
    att_kernel <<<GRID2, 256>>>(kb, ion, Wa, ba, out);
}